// round 16
// baseline (speedup 1.0000x reference)
#include <cuda_runtime.h>
#include <math_constants.h>

// EvalEig: eigenvalues of 16 symmetric tridiagonal matrices (B=4, L=4, N=2000)
// 3-SEGMENT single-sweep Sturm. 9 blocks/matrix x 384 threads; the 2000-step
// recurrence is split across three warp groups on the SAME probes:
//   group 0: pairs    1.. 672  (exact fresh start)            672 steps
//   group 1: pairs  673..1344  (fresh start @577, 96 warm-up) 768 steps
//   group 2: pairs 1345..2000  (fresh start @1249, 96 warm-up)752 steps
// Warm-up counts discarded; each interior boundary contributes at most a +-1
// count blip (interlacing), which the emit coverage rule tolerates.
// Each thread: 2 packed probes; block covers 256 probes of a 2296-point
// split grid. Emit: adjacent probe pairs write bracketed eigenvalues at the
// bracket midpoint. Recurrence (scaled, offdiag=1):
//   q_i = fma(sigma_i*(a_i - x), q_{i-1}, q_{i-2}), sigma=-1 odd i.
// Fresh starts at even 16-step tiles keep step == 1 mod 4 (sign parity ok).

#define RN       2000
#define NMAT     16
#define NTHREADS 384
#define GRP_T    128
#define BLKS_PER_MAT 9
#define PROBE_STRIDE 255      // block j owns global probes [255j, 255j+255]
#define NGRID    2296
#define NFINE    2000
#define FINE_W   4.85f
#define INV_B    0.0025f      // 1/400
#define BSCALE   400.0f

typedef unsigned long long u64;

__device__ __forceinline__ u64 pack2(float x, float y) {
    u64 r; asm("mov.b64 %0, {%1, %2};" : "=l"(r) : "f"(x), "f"(y)); return r;
}
__device__ __forceinline__ u64 add2(u64 a, u64 b) {
    u64 d; asm("add.rn.f32x2 %0, %1, %2;" : "=l"(d) : "l"(a), "l"(b)); return d;
}
__device__ __forceinline__ u64 fma2(u64 a, u64 b, u64 c) {
    u64 d; asm("fma.rn.f32x2 %0, %1, %2, %3;" : "=l"(d) : "l"(a), "l"(b), "l"(c)); return d;
}
__device__ __forceinline__ unsigned lo32(u64 x) { return (unsigned)x; }
__device__ __forceinline__ unsigned hi32(u64 x) { return (unsigned)(x >> 32); }

struct Tile { ulonglong2 v[8]; };   // 16 steps of {sa,sa}

__device__ __forceinline__ void load_tile(Tile& t, const ulonglong2* __restrict__ p) {
#pragma unroll
    for (int j = 0; j < 8; j++) t.v[j] = p[j];
}

// 16 recurrence steps (8 A/B double-steps) + exponent-hack rescale.
__device__ __forceinline__ void do16(const Tile& t, u64 pxh, u64 nxh,
                                     u64& qc, u64& qp,
                                     unsigned& mAlo, unsigned& mAhi,
                                     unsigned& mBlo, unsigned& mBhi) {
#pragma unroll
    for (int j = 0; j < 8; j++) {
        u64 qn = fma2(add2(t.v[j].x, pxh), qc, qp);   // odd poly step
        qp = qc; qc = qn;
        mAlo = __funnelshift_l(lo32(qc), mAlo, 1);
        mAhi = __funnelshift_l(hi32(qc), mAhi, 1);
        qn = fma2(add2(t.v[j].y, nxh), qc, qp);       // even poly step
        qp = qc; qc = qn;
        mBlo = __funnelshift_l(lo32(qc), mBlo, 1);
        mBhi = __funnelshift_l(hi32(qc), mBhi, 1);
    }
    unsigned eb0 = lo32(qc) & 0x7F800000u;
    unsigned eb1 = hi32(qc) & 0x7F800000u;
    float s0 = __uint_as_float(0x7F000000u - eb0);    // 2^(-ilogb), > 0
    float s1 = __uint_as_float(0x7F000000u - eb1);
    qc = pack2(__uint_as_float(lo32(qc)) * s0, __uint_as_float(hi32(qc)) * s1);
    qp = pack2(__uint_as_float(lo32(qp)) * s0, __uint_as_float(hi32(qp)) * s1);
}

// Generic segment: nwin 32-step windows starting at 16-step tile tile0 (must
// be even), first warm windows discarded, optional 16-step tail.
__device__ __forceinline__ void sturm2_seg(const u64* __restrict__ sdp,
                                           float x1, float x2,
                                           int tile0, int nwin, int warm, bool tail,
                                           int& c1, int& c2) {
    const u64 pxh = pack2( x1,  x2);
    const u64 nxh = pack2(-x1, -x2);
    const ulonglong2* __restrict__ p =
        reinterpret_cast<const ulonglong2*>(sdp) + tile0 * 8;
    u64 qp = 0, qc = pack2(1.0f, 1.0f);
    unsigned mAlo = 0, mAhi = 0, mBlo = 0, mBhi = 0, pBlo = 0, pBhi = 0;
    int clo = 0, chi = 0;

    Tile A, B;
    load_tile(A, p);
#pragma unroll 1
    for (int w = 0; w < nwin; w++) {
        load_tile(B, p + (2 * w + 1) * 8);
        do16(A, pxh, nxh, qc, qp, mAlo, mAhi, mBlo, mBhi);
        load_tile(A, p + (2 * w + 2) * 8);     // stays within sdp (see callers)
        do16(B, pxh, nxh, qc, qp, mAlo, mAhi, mBlo, mBhi);
        clo += __popc((mAlo ^ mBlo) & 0xFFFFu)
             + __popc((~(mBlo ^ (mAlo << 1))) & 0xFFFEu)
             + (int)((~(pBlo ^ (mAlo >> 15))) & 1u);
        chi += __popc((mAhi ^ mBhi) & 0xFFFFu)
             + __popc((~(mBhi ^ (mAhi << 1))) & 0xFFFEu)
             + (int)((~(pBhi ^ (mAhi >> 15))) & 1u);
        pBlo = mBlo & 1u; pBhi = mBhi & 1u;
        if (w == warm - 1) { clo = 0; chi = 0; }   // discard warm-up
    }
    if (tail) {   // 16 more steps (8 A-bits, 8 B-bits)
        do16(A, pxh, nxh, qc, qp, mAlo, mAhi, mBlo, mBhi);
        clo += __popc((mAlo ^ mBlo) & 0xFFu)
             + __popc((~(mBlo ^ (mAlo << 1))) & 0xFEu)
             + (int)((~(pBlo ^ (mAlo >> 7))) & 1u);
        chi += __popc((mAhi ^ mBhi) & 0xFFu)
             + __popc((~(mBhi ^ (mAhi << 1))) & 0xFEu)
             + (int)((~(pBhi ^ (mAhi >> 7))) & 1u);
    }
    c1 = clo; c2 = chi;
}

__global__ __launch_bounds__(NTHREADS, 1)
void eval_eig_kernel(const float* __restrict__ ptl, float* __restrict__ out) {
    __shared__ __align__(16) u64 sdp[RN];      // {sigma_i*a_i, same} packed
    __shared__ int   sc[3][2 * GRP_T];         // per-segment counts per probe
    __shared__ float wmin[NTHREADS / 32], wmax[NTHREADS / 32];
    __shared__ float bounds[2];

    const int mat = blockIdx.y;                // 0..15 -> (b, l)
    const int b   = mat >> 2;
    const int l   = mat & 3;
    const float ll1 = (float)(l * (l + 1));
    const int t   = threadIdx.x;

    // Scaled, signed, duplicated diagonal; Gershgorin min/max of a.
    // Bitwise-identical across the matrix's 9 blocks (boundary determinism).
    const float step = 99.95f / 1999.0f;       // jnp.linspace(0.05, 100, 2000)
    float lmin = CUDART_INF_F, lmax = -CUDART_INF_F;
    for (int i = t; i < RN; i += NTHREADS) {
        float r  = 0.05f + step * (float)i;
        float a  = (800.0f + ptl[b * RN + i] + ll1 / (r * r)) * INV_B;
        float sa = (i & 1) ? a : -a;
        sdp[i] = pack2(sa, sa);
        lmin = fminf(lmin, a);
        lmax = fmaxf(lmax, a);
    }
#pragma unroll
    for (int off = 16; off; off >>= 1) {
        lmin = fminf(lmin, __shfl_xor_sync(0xffffffffu, lmin, off));
        lmax = fmaxf(lmax, __shfl_xor_sync(0xffffffffu, lmax, off));
    }
    const int wid = t >> 5;
    if ((t & 31) == 0) { wmin[wid] = lmin; wmax[wid] = lmax; }
    __syncthreads();
    if (t == 0) {
        float a = wmin[0], c = wmax[0];
#pragma unroll
        for (int w = 1; w < NTHREADS / 32; w++) {
            a = fminf(a, wmin[w]);
            c = fmaxf(c, wmax[w]);
        }
        bounds[0] = a - 2.001f;    // count(b0)=0
        bounds[1] = c + 2.001f;    // count(b1)=RN
    }
    __syncthreads();

    const float b0 = bounds[0];
    const float b1 = bounds[1];
    const float cs = fminf(b0 + FINE_W, b1);
    const float gwf = (cs - b0) * (1.0f / (float)NFINE);
    const float gwc = (b1 - cs) * (1.0f / (float)(NGRID - 1 - NFINE));

    auto gridx = [&](int g) -> float {
        return (g <= NFINE) ? b0 + gwf * (float)g
                            : cs + gwc * (float)(g - NFINE);
    };

    // ---- Segmented sweep: 256 probes/block, 2/thread, 3 segments ----
    // Seg 0: tiles  0..41,  21 windows, warm 0, no tail  (steps    1.. 672)
    // Seg 1: tiles 36..83,  24 windows, warm 3, no tail  (steps  577..1344,
    //                                                     counted 673..1344)
    // Seg 2: tiles 78..124, 23 windows, warm 3, +tail    (steps 1249..2000,
    //                                                     counted 1345..2000)
    const int g0  = blockIdx.x * PROBE_STRIDE;
    const int grp = t / GRP_T;                 // 0,1,2
    const int pid = t % GRP_T;
    {
        float x1 = gridx(g0 + 2 * pid);
        float x2 = gridx(g0 + 2 * pid + 1);
        int c1, c2;
        if (grp == 0)      sturm2_seg(sdp, x1, x2,  0, 21, 0, false, c1, c2);
        else if (grp == 1) sturm2_seg(sdp, x1, x2, 36, 24, 3, false, c1, c2);
        else               sturm2_seg(sdp, x1, x2, 78, 23, 3, true,  c1, c2);
        sc[grp][2 * pid]     = c1;
        sc[grp][2 * pid + 1] = c2;
    }
    __syncthreads();

    // ---- Emit (group 0): pair (u, u+1) writes eigenvalues [c[u], c[u+1])
    // at the bracket midpoint. Coverage: the last u with c[u] <= k has
    // c[u+1] > k (c sums to 0 at global left edge, RN at right; boundary
    // probes bitwise-duplicated across blocks), so every k is written even
    // with +-1 boundary blips.
    if (grp == 0) {
#pragma unroll
        for (int h = 0; h < 2; h++) {
            int u = 2 * pid + h;
            if (u < 2 * GRP_T - 1) {
                int cL = sc[0][u] + sc[1][u] + sc[2][u];
                int cR = sc[0][u + 1] + sc[1][u + 1] + sc[2][u + 1];
                if (cR > cL) {
                    float xm = 0.5f * (gridx(g0 + u) + gridx(g0 + u + 1)) * BSCALE;
                    cL = max(cL, 0); cR = min(cR, RN);
                    for (int k = cL; k < cR; k++) out[mat * RN + k] = xm;
                }
            }
        }
    }
}

extern "C" void kernel_launch(void* const* d_in, const int* in_sizes, int n_in,
                              void* d_out, int out_size) {
    (void)in_sizes; (void)n_in; (void)out_size;
    const float* ptl = (const float*)d_in[0];
    float* out = (float*)d_out;
    dim3 grid(BLKS_PER_MAT, NMAT);   // (9, 16) = 144 blocks, 384 threads
    eval_eig_kernel<<<grid, NTHREADS>>>(ptl, out);
}

// round 17
// speedup vs baseline: 1.1065x; 1.1065x over previous
#include <cuda_runtime.h>
#include <math_constants.h>

// EvalEig: eigenvalues of 16 symmetric tridiagonal matrices (B=4, L=4, N=2000)
// EXACT two-sided segmented Sturm sweep. 9 blocks/matrix x 256 threads:
//   threads [0,128):   FORWARD rows 1..1008 (fresh start, exact)
//   threads [128,256): BACKWARD rows 2000..1009 (fresh start, exact)
// Twisted-factorization junction (exact, no warm-up):
//   neg(T) = negF + (cB - [E<0]) + [E - 1/D < 0]
//   D = p1008/p1007 = qcF/qpF;  E = Etilde_1009 = -uc/up;  [E<0] = [uc*up>0]
//   [E-1/D<0] = (w>0) XOR (den<0), w = uc*qcF+up*qpF, den = up*qcF.
// Probes: 2 packed f32x2 per thread; block covers 256 probes of a 2296-point
// split grid (stride 255 between blocks); emit writes bracketed eigenvalues
// at bracket midpoints. Recurrence (scaled, offdiag=1):
//   q_i = fma(sigma_i*(a_i-x), q_{i-1}, q_{i-2}), sigma=-1 odd i (eps=+,-,-,+).
// Backward runs the reversed array (eta=+,+,-,-): its sign-change flip
// constants are the COMPLEMENT of the forward ones.

#define RN       2000
#define NMAT     16
#define NTHREADS 256
#define HALF_T   128
#define BLKS_PER_MAT 9
#define PROBE_STRIDE 255
#define NGRID    2296
#define NFINE    2000
#define FINE_W   4.85f
#define INV_B    0.0025f
#define BSCALE   400.0f
#define FWD_WIN  31            // 31*32 + 16 tail = 1008 steps (tiles 0..62)
#define BWD_WIN  31            // 31*32 = 992 steps (tiles 124..63, descending)

typedef unsigned long long u64;

__device__ __forceinline__ u64 pack2(float x, float y) {
    u64 r; asm("mov.b64 %0, {%1, %2};" : "=l"(r) : "f"(x), "f"(y)); return r;
}
__device__ __forceinline__ u64 add2(u64 a, u64 b) {
    u64 d; asm("add.rn.f32x2 %0, %1, %2;" : "=l"(d) : "l"(a), "l"(b)); return d;
}
__device__ __forceinline__ u64 fma2(u64 a, u64 b, u64 c) {
    u64 d; asm("fma.rn.f32x2 %0, %1, %2, %3;" : "=l"(d) : "l"(a), "l"(b), "l"(c)); return d;
}
__device__ __forceinline__ unsigned lo32(u64 x) { return (unsigned)x; }
__device__ __forceinline__ unsigned hi32(u64 x) { return (unsigned)(x >> 32); }

struct Tile { ulonglong2 v[8]; };

__device__ __forceinline__ void load_tile(Tile& t, const ulonglong2* __restrict__ p) {
#pragma unroll
    for (int j = 0; j < 8; j++) t.v[j] = p[j];
}

#define RESCALE()                                                              \
    do {                                                                       \
        unsigned eb0 = lo32(qc) & 0x7F800000u;                                 \
        unsigned eb1 = hi32(qc) & 0x7F800000u;                                 \
        float s0 = __uint_as_float(0x7F000000u - eb0);                         \
        float s1 = __uint_as_float(0x7F000000u - eb1);                         \
        qc = pack2(__uint_as_float(lo32(qc)) * s0, __uint_as_float(hi32(qc)) * s1); \
        qp = pack2(__uint_as_float(lo32(qp)) * s0, __uint_as_float(hi32(qp)) * s1); \
    } while (0)

// 16 forward steps: even idx (+x addend) -> mA (odd poly step), odd idx -> mB.
__device__ __forceinline__ void do16_fwd(const Tile& t, u64 pxh, u64 nxh,
                                         u64& qc, u64& qp,
                                         unsigned& mAlo, unsigned& mAhi,
                                         unsigned& mBlo, unsigned& mBhi) {
#pragma unroll
    for (int j = 0; j < 8; j++) {
        u64 qn = fma2(add2(t.v[j].x, pxh), qc, qp);
        qp = qc; qc = qn;
        mAlo = __funnelshift_l(lo32(qc), mAlo, 1);
        mAhi = __funnelshift_l(hi32(qc), mAhi, 1);
        qn = fma2(add2(t.v[j].y, nxh), qc, qp);
        qp = qc; qc = qn;
        mBlo = __funnelshift_l(lo32(qc), mBlo, 1);
        mBhi = __funnelshift_l(hi32(qc), mBhi, 1);
    }
    RESCALE();
}

// 16 backward steps (descending idx): odd idx (-x addend) -> mA (odd bwd
// step), even idx (+x) -> mB (even bwd step).
__device__ __forceinline__ void do16_bwd(const Tile& t, u64 pxh, u64 nxh,
                                         u64& qc, u64& qp,
                                         unsigned& mAlo, unsigned& mAhi,
                                         unsigned& mBlo, unsigned& mBhi) {
#pragma unroll
    for (int j = 7; j >= 0; j--) {
        u64 qn = fma2(add2(t.v[j].y, nxh), qc, qp);
        qp = qc; qc = qn;
        mAlo = __funnelshift_l(lo32(qc), mAlo, 1);
        mAhi = __funnelshift_l(hi32(qc), mAhi, 1);
        qn = fma2(add2(t.v[j].x, pxh), qc, qp);
        qp = qc; qc = qn;
        mBlo = __funnelshift_l(lo32(qc), mBlo, 1);
        mBhi = __funnelshift_l(hi32(qc), mBhi, 1);
    }
    RESCALE();
}

// Normalize (c, p) by 2^-ilogb(max|.|): ratio preserved, products overflow-safe.
__device__ __forceinline__ float2 norm_pair(float c, float p) {
    float m = fmaxf(fabsf(c), fabsf(p));
    unsigned eb = __float_as_uint(m) & 0x7F800000u;
    float s = __uint_as_float(0x7F000000u - eb);
    return make_float2(c * s, p * s);
}

// FORWARD: rows 1..1008. Counts + final (qc,qp).
__device__ __forceinline__ void sturm2_fwd(const u64* __restrict__ sdp,
                                           float x1, float x2,
                                           int& c1, int& c2, float2& j1, float2& j2) {
    const u64 pxh = pack2( x1,  x2);
    const u64 nxh = pack2(-x1, -x2);
    const ulonglong2* __restrict__ p = reinterpret_cast<const ulonglong2*>(sdp);
    u64 qp = 0, qc = pack2(1.0f, 1.0f);
    unsigned mAlo = 0, mAhi = 0, mBlo = 0, mBhi = 0, pBlo = 0, pBhi = 0;
    int clo = 0, chi = 0;

    Tile A, B;
    load_tile(A, p);
#pragma unroll 1
    for (int w = 0; w < FWD_WIN; w++) {
        load_tile(B, p + (2 * w + 1) * 8);
        do16_fwd(A, pxh, nxh, qc, qp, mAlo, mAhi, mBlo, mBhi);
        load_tile(A, p + (2 * w + 2) * 8);        // max tile 62: in bounds
        do16_fwd(B, pxh, nxh, qc, qp, mAlo, mAhi, mBlo, mBhi);
        clo += __popc((mAlo ^ mBlo) & 0xFFFFu)               // end-even: no flip
             + __popc((~(mBlo ^ (mAlo << 1))) & 0xFFFEu)     // end-odd: flip
             + (int)((~(pBlo ^ (mAlo >> 15))) & 1u);         // boundary: flip
        chi += __popc((mAhi ^ mBhi) & 0xFFFFu)
             + __popc((~(mBhi ^ (mAhi << 1))) & 0xFFFEu)
             + (int)((~(pBhi ^ (mAhi >> 15))) & 1u);
        pBlo = mBlo & 1u; pBhi = mBhi & 1u;
    }
    do16_fwd(A, pxh, nxh, qc, qp, mAlo, mAhi, mBlo, mBhi);   // tail: tile 62
    clo += __popc((mAlo ^ mBlo) & 0xFFu)
         + __popc((~(mBlo ^ (mAlo << 1))) & 0xFEu)
         + (int)((~(pBlo ^ (mAlo >> 7))) & 1u);
    chi += __popc((mAhi ^ mBhi) & 0xFFu)
         + __popc((~(mBhi ^ (mAhi << 1))) & 0xFEu)
         + (int)((~(pBhi ^ (mAhi >> 7))) & 1u);
    c1 = clo; c2 = chi;
    j1 = norm_pair(__uint_as_float(lo32(qc)), __uint_as_float(lo32(qp)));
    j2 = norm_pair(__uint_as_float(hi32(qc)), __uint_as_float(hi32(qp)));
}

// BACKWARD: rows 2000 down to 1009. Counts + final (uc,up).
__device__ __forceinline__ void sturm2_bwd(const u64* __restrict__ sdp,
                                           float x1, float x2,
                                           int& c1, int& c2, float2& j1, float2& j2) {
    const u64 pxh = pack2( x1,  x2);
    const u64 nxh = pack2(-x1, -x2);
    const ulonglong2* __restrict__ p = reinterpret_cast<const ulonglong2*>(sdp);
    u64 qp = 0, qc = pack2(1.0f, 1.0f);
    unsigned mAlo = 0, mAhi = 0, mBlo = 0, mBhi = 0, pBlo = 0, pBhi = 0;
    int clo = 0, chi = 0;

    Tile A, B;
    load_tile(A, p + 124 * 8);
#pragma unroll 1
    for (int w = 0; w < BWD_WIN; w++) {
        load_tile(B, p + (123 - 2 * w) * 8);
        do16_bwd(A, pxh, nxh, qc, qp, mAlo, mAhi, mBlo, mBhi);
        load_tile(A, p + (122 - 2 * w) * 8);      // min tile 62 >= 0: in bounds
        do16_bwd(B, pxh, nxh, qc, qp, mAlo, mAhi, mBlo, mBhi);
        clo += __popc((~(mAlo ^ mBlo)) & 0xFFFFu)            // end-even: flip
             + __popc((mBlo ^ (mAlo << 1)) & 0xFFFEu)        // end-odd: no flip
             + (int)((pBlo ^ (mAlo >> 15)) & 1u);            // boundary: no flip
        chi += __popc((~(mAhi ^ mBhi)) & 0xFFFFu)
             + __popc((mBhi ^ (mAhi << 1)) & 0xFFFEu)
             + (int)((pBhi ^ (mAhi >> 15)) & 1u);
        pBlo = mBlo & 1u; pBhi = mBhi & 1u;
    }
    c1 = clo; c2 = chi;
    j1 = norm_pair(__uint_as_float(lo32(qc)), __uint_as_float(lo32(qp)));
    j2 = norm_pair(__uint_as_float(hi32(qc)), __uint_as_float(hi32(qp)));
}

__global__ __launch_bounds__(NTHREADS, 1)
void eval_eig_kernel(const float* __restrict__ ptl, float* __restrict__ out) {
    __shared__ __align__(16) u64 sdp[RN];
    __shared__ int    scF[2 * HALF_T], scB[2 * HALF_T], scC[2 * HALF_T];
    __shared__ float2 jF[2 * HALF_T], jB[2 * HALF_T];
    __shared__ float  wmin[NTHREADS / 32], wmax[NTHREADS / 32];
    __shared__ float  bounds[2];

    const int mat = blockIdx.y;
    const int b   = mat >> 2;
    const int l   = mat & 3;
    const float ll1 = (float)(l * (l + 1));
    const int t   = threadIdx.x;

    const float step = 99.95f / 1999.0f;
    float lmin = CUDART_INF_F, lmax = -CUDART_INF_F;
    for (int i = t; i < RN; i += NTHREADS) {
        float r  = 0.05f + step * (float)i;
        float a  = (800.0f + ptl[b * RN + i] + ll1 / (r * r)) * INV_B;
        float sa = (i & 1) ? a : -a;
        sdp[i] = pack2(sa, sa);
        lmin = fminf(lmin, a);
        lmax = fmaxf(lmax, a);
    }
#pragma unroll
    for (int off = 16; off; off >>= 1) {
        lmin = fminf(lmin, __shfl_xor_sync(0xffffffffu, lmin, off));
        lmax = fmaxf(lmax, __shfl_xor_sync(0xffffffffu, lmax, off));
    }
    const int wid = t >> 5;
    if ((t & 31) == 0) { wmin[wid] = lmin; wmax[wid] = lmax; }
    __syncthreads();
    if (t == 0) {
        float a = wmin[0], c = wmax[0];
#pragma unroll
        for (int w = 1; w < NTHREADS / 32; w++) {
            a = fminf(a, wmin[w]);
            c = fmaxf(c, wmax[w]);
        }
        bounds[0] = a - 2.001f;
        bounds[1] = c + 2.001f;
    }
    __syncthreads();

    const float b0 = bounds[0];
    const float b1 = bounds[1];
    const float cs = fminf(b0 + FINE_W, b1);
    const float gwf = (cs - b0) * (1.0f / (float)NFINE);
    const float gwc = (b1 - cs) * (1.0f / (float)(NGRID - 1 - NFINE));

    auto gridx = [&](int g) -> float {
        return (g <= NFINE) ? b0 + gwf * (float)g
                            : cs + gwc * (float)(g - NFINE);
    };

    // ---- Two-sided sweep: 256 probes/block, 2/thread ----
    const int g0  = blockIdx.x * PROBE_STRIDE;
    const int pid = t & (HALF_T - 1);
    {
        float x1 = gridx(g0 + 2 * pid);
        float x2 = gridx(g0 + 2 * pid + 1);
        int c1, c2; float2 j1, j2;
        if (t < HALF_T) {
            sturm2_fwd(sdp, x1, x2, c1, c2, j1, j2);
            scF[2 * pid] = c1; scF[2 * pid + 1] = c2;
            jF[2 * pid] = j1;  jF[2 * pid + 1] = j2;
        } else {
            sturm2_bwd(sdp, x1, x2, c1, c2, j1, j2);
            scB[2 * pid] = c1; scB[2 * pid + 1] = c2;
            jB[2 * pid] = j1;  jB[2 * pid + 1] = j2;
        }
    }
    __syncthreads();

    // ---- Exact junction composition, one probe per thread ----
    {
        int c = scF[t] + scB[t];
        float2 f = jF[t];                    // (qcF, qpF): D = qcF/qpF
        float2 g = jB[t];                    // (uc, up):   E = -uc/up
        if (g.x * g.y > 0.0f) c -= 1;        // remove [E < 0] from cB
        float w   = fmaf(g.x, f.x, g.y * f.y);
        float den = g.y * f.x;
        if ((w > 0.0f) != (den < 0.0f)) c += 1;   // add [E - 1/D < 0]
        scC[t] = c;
    }
    __syncthreads();

    // ---- Emit (lower half): pair (u, u+1) writes eigenvalues in
    // [scC[u], scC[u+1]) at the bracket midpoint; telescoping coverage.
    if (t < HALF_T) {
#pragma unroll
        for (int h = 0; h < 2; h++) {
            int u = 2 * pid + h;
            if (u < 2 * HALF_T - 1) {
                int cL = scC[u], cR = scC[u + 1];
                if (cR > cL) {
                    float xm = 0.5f * (gridx(g0 + u) + gridx(g0 + u + 1)) * BSCALE;
                    cL = max(cL, 0); cR = min(cR, RN);
                    for (int k = cL; k < cR; k++) out[mat * RN + k] = xm;
                }
            }
        }
    }
}

extern "C" void kernel_launch(void* const* d_in, const int* in_sizes, int n_in,
                              void* d_out, int out_size) {
    (void)in_sizes; (void)n_in; (void)out_size;
    const float* ptl = (const float*)d_in[0];
    float* out = (float*)d_out;
    dim3 grid(BLKS_PER_MAT, NMAT);   // (9, 16) = 144 blocks, 256 threads
    eval_eig_kernel<<<grid, NTHREADS>>>(ptl, out);
}